// round 2
// baseline (speedup 1.0000x reference)
#include <cuda_runtime.h>
#include <cstdint>

// SNN_Delay: 3x (DCLS gaussian 11-tap temporal conv -> [BN] -> LIF scan), forward only.
// This round: accuracy-maximized build. Conv dot products use error-free TwoSum
// compensated fp32 accumulation; weight prep + LIF scans run in fp64 internally.

#define NT 25
#define NB 1024
#define MROWS (NB*NT)          // 25600
#define K1TOT (11*140)         // 1540
#define K2TOT (11*256)         // 2816

// scratch (static device allocations are allowed)
__device__ float g_Wg1[K1TOT*256];
__device__ float g_Wg2[K2TOT*256];
__device__ float g_Wg3[K2TOT*20];
__device__ float g_bb1[256];
__device__ float g_bb2[256];
__device__ float g_bb3[20];
__device__ float g_Y[MROWS*256];
__device__ float g_S1[MROWS*256];
__device__ float g_S2[MROWS*256];
__device__ float g_Y3[MROWS*20];

// ---------------------------------------------------------------------------
// Weight prep (fp64 internal): dense DCLS kernel, normalized gaussian taps,
// BN scale folded in. Wg layout: [k = j*I + i][o]  (o contiguous).
// ---------------------------------------------------------------------------
__global__ void prep_weights(const float* __restrict__ W, const float* __restrict__ P,
                             const float* __restrict__ SIG, const float* __restrict__ gamma,
                             const float* __restrict__ var, float* __restrict__ Wg,
                             int O, int I)
{
    int idx = blockIdx.x * blockDim.x + threadIdx.x;
    if (idx >= O * I) return;
    int o = idx / I;
    int i = idx - o * I;
    double pc = (double)P[idx] + 5.0;          // MAXD//2 = 5
    double s  = fabs((double)SIG[idx]) + 0.27;
    double g[11];
    double sum = 0.0;
#pragma unroll
    for (int j = 0; j < 11; j++) {
        double d = ((double)j - pc) / s;
        g[j] = exp(-0.5 * d * d);
        sum += g[j];
    }
    double scale = (double)W[idx] / (sum + 1e-7);
    if (gamma) scale *= (double)gamma[o] / sqrt((double)var[o] + 1e-5);
#pragma unroll
    for (int j = 0; j < 11; j++)
        Wg[(size_t)(j * I + i) * O + o] = (float)(g[j] * scale);
}

__global__ void prep_bias(const float* __restrict__ b, const float* __restrict__ gamma,
                          const float* __restrict__ beta, const float* __restrict__ mean,
                          const float* __restrict__ var, float* __restrict__ out, int O)
{
    int o = blockIdx.x * blockDim.x + threadIdx.x;
    if (o >= O) return;
    double v = (double)b[o];
    if (gamma) {
        double sc = (double)gamma[o] / sqrt((double)var[o] + 1e-5);
        v = (v - (double)mean[o]) * sc + (double)beta[o];
    }
    out[o] = (float)v;
}

// ---------------------------------------------------------------------------
// Implicit-GEMM conv with compensated (TwoSum) fp32 accumulation.
// C[m,n] = sum_k U[m,k]*Wg[k,n] + bias[n],
//   U[m,k] = X[(m-10)*I + k] if k >= (10 - m%25)*I else 0.
// BM=128 BN=64 BK=16, 256 threads, 8x4 microtile.
// ---------------------------------------------------------------------------
__global__ void __launch_bounds__(256)
conv_gemm_kh(const float* __restrict__ X, const float* __restrict__ Wg,
             const float* __restrict__ bias, float* __restrict__ Y,
             int N, int Ktot, int I)
{
    __shared__ float As[16][136];   // 136: pad, rows stay 16B-aligned (544B)
    __shared__ float Bs[16][68];    // 68:  pad, rows stay 16B-aligned (272B)

    const int tid = threadIdx.x;
    const int bm = blockIdx.x * 128;
    const int bn = blockIdx.y * 64;

    // A-load geometry: 2 rows per thread, one float4 of k each
    const int arow = tid >> 2;          // 0..63
    const int akq  = (tid & 3) * 4;     // 0,4,8,12
    long abase[2];
    int  alow[2];
#pragma unroll
    for (int r = 0; r < 2; r++) {
        int m = bm + arow + r * 64;
        int t = m % 25;
        abase[r] = (long)(m - 10) * I;
        alow[r]  = (t < 10) ? (10 - t) * I : 0;   // multiple of 4 (I%4==0)
    }
    // B-load geometry: 1 float4 per thread covers the 16x64 tile
    const int brow = tid >> 4;          // 0..15
    const int bcq  = (tid & 15) * 4;    // 0..60

    float acc[8][4], cmp[8][4];
#pragma unroll
    for (int q = 0; q < 8; q++)
#pragma unroll
        for (int p = 0; p < 4; p++) { acc[q][p] = 0.f; cmp[q][p] = 0.f; }

    const int ty = tid >> 4;            // 0..15 -> 8-row group
    const int tx = tid & 15;            // 0..15 -> 4-col group

    for (int k0 = 0; k0 < Ktot; k0 += 16) {
#pragma unroll
        for (int r = 0; r < 2; r++) {
            int k = k0 + akq;
            float4 v = make_float4(0.f, 0.f, 0.f, 0.f);
            if (k >= alow[r] && k < Ktot)       // Ktot%4==0 -> vector-exact
                v = *reinterpret_cast<const float4*>(X + abase[r] + k);
            int row = arow + r * 64;
            As[akq + 0][row] = v.x;
            As[akq + 1][row] = v.y;
            As[akq + 2][row] = v.z;
            As[akq + 3][row] = v.w;
        }
        {
            int k = k0 + brow;
            int n = bn + bcq;
            float4 v = make_float4(0.f, 0.f, 0.f, 0.f);
            if (k < Ktot && n < N)              // N%4==0 -> vector-exact
                v = *reinterpret_cast<const float4*>(Wg + (size_t)k * N + n);
            *reinterpret_cast<float4*>(&Bs[brow][bcq]) = v;
        }
        __syncthreads();

#pragma unroll
        for (int kk = 0; kk < 16; kk++) {
            float4 a0 = *reinterpret_cast<const float4*>(&As[kk][ty * 8]);
            float4 a1 = *reinterpret_cast<const float4*>(&As[kk][ty * 8 + 4]);
            float4 bv = *reinterpret_cast<const float4*>(&Bs[kk][tx * 4]);
            float av[8] = {a0.x, a0.y, a0.z, a0.w, a1.x, a1.y, a1.z, a1.w};
            float bw[4] = {bv.x, bv.y, bv.z, bv.w};
#pragma unroll
            for (int q = 0; q < 8; q++) {
#pragma unroll
                for (int p = 0; p < 4; p++) {
                    // error-free TwoSum accumulation of prod into acc, error into cmp
                    float prod = __fmul_rn(av[q], bw[p]);
                    float s    = acc[q][p];
                    float t    = __fadd_rn(s, prod);
                    float z    = __fsub_rn(t, s);
                    float e    = __fadd_rn(__fsub_rn(s, __fsub_rn(t, z)),
                                           __fsub_rn(prod, z));
                    acc[q][p]  = t;
                    cmp[q][p]  = __fadd_rn(cmp[q][p], e);
                }
            }
        }
        __syncthreads();
    }

#pragma unroll
    for (int q = 0; q < 8; q++) {
        int m = bm + ty * 8 + q;
#pragma unroll
        for (int p = 0; p < 4; p++) {
            int n = bn + tx * 4 + p;
            if (n < N) {
                float v = __fadd_rn(acc[q][p], cmp[q][p]);
                Y[(size_t)m * N + n] = __fadd_rn(v, bias[n]);
            }
        }
    }
}

// ---------------------------------------------------------------------------
// LIF scan in fp64 (snntorch Leaky, reset='subtract'). Layout (B,T,C).
// ---------------------------------------------------------------------------
__global__ void lif_kernel(const float* __restrict__ Y, float* __restrict__ S, int C)
{
    int idx = blockIdx.x * blockDim.x + threadIdx.x;
    if (idx >= NB * C) return;
    int b = idx / C;
    int c = idx - b * C;
    const float* y = Y + (size_t)b * NT * C + c;
    float* s = S + (size_t)b * NT * C + c;
    double mem = 0.0;
#pragma unroll
    for (int t = 0; t < NT; t++) {
        double reset = (mem > 1.0) ? 1.0 : 0.0;
        mem = 0.95 * mem + (double)y[t * C] - reset;
        s[t * C] = (mem > 1.0) ? 1.0f : 0.0f;
    }
}

// Final LIF: emits spk3 (T,B,20) then mem3 (T,B,20) into d_out.
__global__ void lif_out_kernel(const float* __restrict__ Y, float* __restrict__ out,
                               int out_size)
{
    int idx = blockIdx.x * blockDim.x + threadIdx.x;
    if (idx >= NB * 20) return;
    int b = idx / 20;
    int c = idx - b * 20;
    bool have_mem = (out_size >= 2 * NT * NB * 20);
    double mem = 0.0;
#pragma unroll
    for (int t = 0; t < NT; t++) {
        double reset = (mem > 1.0) ? 1.0 : 0.0;
        mem = 0.95 * mem + (double)Y[((size_t)b * NT + t) * 20 + c] - reset;
        float spk = (mem > 1.0) ? 1.0f : 0.0f;
        out[(size_t)t * NB * 20 + b * 20 + c] = spk;
        if (have_mem)
            out[(size_t)NT * NB * 20 + (size_t)t * NB * 20 + b * 20 + c] = (float)mem;
    }
}

// ---------------------------------------------------------------------------
extern "C" void kernel_launch(void* const* d_in, const int* in_sizes, int n_in,
                              void* d_out, int out_size)
{
    const float* data = (const float*)d_in[0];
    const float* W1   = (const float*)d_in[1];
    const float* b1   = (const float*)d_in[2];
    const float* P1   = (const float*)d_in[3];
    const float* SIG1 = (const float*)d_in[4];
    const float* g1   = (const float*)d_in[5];
    const float* be1  = (const float*)d_in[6];
    const float* mu1  = (const float*)d_in[7];
    const float* va1  = (const float*)d_in[8];
    const float* W2   = (const float*)d_in[9];
    const float* b2   = (const float*)d_in[10];
    const float* P2   = (const float*)d_in[11];
    const float* SIG2 = (const float*)d_in[12];
    const float* g2   = (const float*)d_in[13];
    const float* be2  = (const float*)d_in[14];
    const float* mu2  = (const float*)d_in[15];
    const float* va2  = (const float*)d_in[16];
    const float* W3   = (const float*)d_in[17];
    const float* b3   = (const float*)d_in[18];
    const float* P3   = (const float*)d_in[19];
    const float* SIG3 = (const float*)d_in[20];

    float *Wg1, *Wg2, *Wg3, *bb1, *bb2, *bb3, *Y, *S1, *S2, *Y3;
    cudaGetSymbolAddress((void**)&Wg1, g_Wg1);
    cudaGetSymbolAddress((void**)&Wg2, g_Wg2);
    cudaGetSymbolAddress((void**)&Wg3, g_Wg3);
    cudaGetSymbolAddress((void**)&bb1, g_bb1);
    cudaGetSymbolAddress((void**)&bb2, g_bb2);
    cudaGetSymbolAddress((void**)&bb3, g_bb3);
    cudaGetSymbolAddress((void**)&Y,   g_Y);
    cudaGetSymbolAddress((void**)&S1,  g_S1);
    cudaGetSymbolAddress((void**)&S2,  g_S2);
    cudaGetSymbolAddress((void**)&Y3,  g_Y3);

    // weight/bias prep (tiny)
    prep_weights<<<(256 * 140 + 255) / 256, 256>>>(W1, P1, SIG1, g1, va1, Wg1, 256, 140);
    prep_weights<<<(256 * 256 + 255) / 256, 256>>>(W2, P2, SIG2, g2, va2, Wg2, 256, 256);
    prep_weights<<<(20 * 256 + 255) / 256, 256>>>(W3, P3, SIG3, nullptr, nullptr, Wg3, 20, 256);
    prep_bias<<<1, 256>>>(b1, g1, be1, mu1, va1, bb1, 256);
    prep_bias<<<1, 256>>>(b2, g2, be2, mu2, va2, bb2, 256);
    prep_bias<<<1, 32>>>(b3, nullptr, nullptr, nullptr, nullptr, bb3, 20);

    // layer 1: conv(140->256) + BN folded, then LIF
    conv_gemm_kh<<<dim3(200, 4), 256>>>(data, Wg1, bb1, Y, 256, K1TOT, 140);
    lif_kernel<<<(NB * 256 + 255) / 256, 256>>>(Y, S1, 256);

    // layer 2
    conv_gemm_kh<<<dim3(200, 4), 256>>>(S1, Wg2, bb2, Y, 256, K2TOT, 256);
    lif_kernel<<<(NB * 256 + 255) / 256, 256>>>(Y, S2, 256);

    // layer 3 (N=20, no BN)
    conv_gemm_kh<<<dim3(200, 1), 256>>>(S2, Wg3, bb3, Y3, 20, K2TOT, 256);
    lif_out_kernel<<<(NB * 20 + 255) / 256, 256>>>(Y3, (float*)d_out, out_size);
}

// round 4
// speedup vs baseline: 1.9906x; 1.9906x over previous
#include <cuda_runtime.h>
#include <cstdint>

// SNN_Delay: 3x (DCLS gaussian 11-tap temporal conv -> [BN] -> LIF scan), forward only.
// Conv = implicit GEMM with biased FastTwoSum compensated accumulation (error-free)
// on packed f32x2 ops: 5 packed fma-pipe ops per 2 scalar MAC terms.
// R4 fix: weight-row stride (Nw, padded) decoupled from output stride (N).

typedef unsigned long long ull;

#define NT 25
#define NB 1024
#define MROWS (NB*NT)          // 25600
#define K1TOT (11*140)         // 1540
#define K2TOT (11*256)         // 2816

// scratch (static device allocations are allowed)
__device__ float g_Wg1[K1TOT*256];
__device__ float g_Wg2[K2TOT*256];
__device__ float g_Wg3[K2TOT*32];
__device__ float g_bb1[256];
__device__ float g_bb2[256];
__device__ float g_bb3[32];
__device__ float g_Y[MROWS*256];
__device__ float g_S1[MROWS*256];
__device__ float g_S2[MROWS*256];
__device__ float g_Y3[MROWS*20];

// ---------------------------------------------------------------------------
// Weight prep (fp64 internal): dense DCLS kernel, normalized gaussian taps,
// BN scale folded in. Wg layout: [k = j*I + i][o]  (o contiguous, Ostride cols).
// ---------------------------------------------------------------------------
__global__ void prep_weights(const float* __restrict__ W, const float* __restrict__ P,
                             const float* __restrict__ SIG, const float* __restrict__ gamma,
                             const float* __restrict__ var, float* __restrict__ Wg,
                             int O, int I, int Ostride)
{
    int idx = blockIdx.x * blockDim.x + threadIdx.x;
    if (idx >= O * I) return;
    int o = idx / I;
    int i = idx - o * I;
    double pc = (double)P[idx] + 5.0;          // MAXD//2 = 5
    double s  = fabs((double)SIG[idx]) + 0.27;
    double g[11];
    double sum = 0.0;
#pragma unroll
    for (int j = 0; j < 11; j++) {
        double d = ((double)j - pc) / s;
        g[j] = exp(-0.5 * d * d);
        sum += g[j];
    }
    double scale = (double)W[idx] / (sum + 1e-7);
    if (gamma) scale *= (double)gamma[o] / sqrt((double)var[o] + 1e-5);
#pragma unroll
    for (int j = 0; j < 11; j++)
        Wg[(size_t)(j * I + i) * Ostride + o] = (float)(g[j] * scale);
}

// zero-fill padded weight columns (layer 3: O=20 padded to 32)
__global__ void zero_buf(float* p, int n)
{
    int i = blockIdx.x * blockDim.x + threadIdx.x;
    if (i < n) p[i] = 0.f;
}

__global__ void prep_bias(const float* __restrict__ b, const float* __restrict__ gamma,
                          const float* __restrict__ beta, const float* __restrict__ mean,
                          const float* __restrict__ var, float* __restrict__ out, int O)
{
    int o = blockIdx.x * blockDim.x + threadIdx.x;
    if (o >= O) return;
    double v = (double)b[o];
    if (gamma) {
        double sc = (double)gamma[o] / sqrt((double)var[o] + 1e-5);
        v = (v - (double)mean[o]) * sc + (double)beta[o];
    }
    out[o] = (float)v;
}

// ---------------------------------------------------------------------------
// packed f32x2 helpers
// ---------------------------------------------------------------------------
__device__ __forceinline__ ull pack2s(float a) {
    ull r; asm("mov.b64 %0, {%1,%1};" : "=l"(r) : "f"(a)); return r;
}
__device__ __forceinline__ void unpack2(ull v, float& x, float& y) {
    asm("mov.b64 {%0,%1}, %2;" : "=f"(x), "=f"(y) : "l"(v));
}
__device__ __forceinline__ ull pmul(ull a, ull b) {
    ull r; asm("mul.rn.f32x2 %0, %1, %2;" : "=l"(r) : "l"(a), "l"(b)); return r;
}
__device__ __forceinline__ ull padd(ull a, ull b) {
    ull r; asm("add.rn.f32x2 %0, %1, %2;" : "=l"(r) : "l"(a), "l"(b)); return r;
}
__device__ __forceinline__ ull pfma(ull a, ull b, ull c) {
    ull r; asm("fma.rn.f32x2 %0, %1, %2, %3;" : "=l"(r) : "l"(a), "l"(b), "l"(c)); return r;
}

#define NEG1_PK  0xBF800000BF800000ULL   // (-1.f, -1.f)
#define CBIAS    512.0f
#define CBIAS_PK 0x4400000044000000ULL   // (512.f, 512.f)

// ---------------------------------------------------------------------------
// Implicit-GEMM conv, biased FastTwoSum accumulation, packed f32x2.
// C[m,n] = sum_k U[m,k]*Wg[k,n] + bias[n],
//   U[m,k] = X[(m-10)*I + k] if k >= (10 - m%25)*I else 0.
// Wg rows have stride Nw (>= N, padded to multiple of BN); Y rows stride N.
// Template: BM x BN tile, 256 threads, 8x4 microtile (2 packed col-pairs).
// ---------------------------------------------------------------------------
template<int BM, int BN>
__global__ void __launch_bounds__(256)
conv_gemm_pk(const float* __restrict__ X, const float* __restrict__ Wg,
             const float* __restrict__ bias, float* __restrict__ Y,
             int N, int Nw, int Ktot, int I)
{
    static_assert(BM / 64 * 64 == BM, "BM multiple of 64");
    constexpr int APASS = BM / 64;       // row passes for A loads
    constexpr int CG    = BN / 4;        // col groups
    static_assert(256 / CG * 8 == BM, "compute map covers BM");
    __shared__ float As[16][BM + 12];    // 16B-aligned rows, conflict-light
    __shared__ float Bs[16][BN + 4];

    const int tid = threadIdx.x;
    const int bm = blockIdx.x * BM;
    const int bn = blockIdx.y * BN;

    // A-load geometry: rows arow + r*64, one float4 of k each
    const int arow = tid >> 2;          // 0..63
    const int akq  = (tid & 3) * 4;     // 0,4,8,12
    long abase[APASS];
    int  alow[APASS];
#pragma unroll
    for (int r = 0; r < APASS; r++) {
        int m = bm + arow + r * 64;
        int t = m % 25;
        abase[r] = (long)(m - 10) * I;
        alow[r]  = (t < 10) ? (10 - t) * I : 0;   // multiple of 4 (I%4==0)
    }
    // B-load geometry: one float4 per k-row slot
    const int bkrow = tid / CG;          // k-row
    const int bcq   = (tid % CG) * 4;    // col offset

    ull acc[8][2], cmp[8][2];
#pragma unroll
    for (int q = 0; q < 8; q++) {
        acc[q][0] = CBIAS_PK; acc[q][1] = CBIAS_PK;
        cmp[q][0] = 0ull;     cmp[q][1] = 0ull;
    }

    const int ty = tid / CG;            // row group (8 rows)
    const int tx = tid % CG;            // col group (4 cols)

    for (int k0 = 0; k0 < Ktot; k0 += 16) {
#pragma unroll
        for (int r = 0; r < APASS; r++) {
            int k = k0 + akq;
            float4 v = make_float4(0.f, 0.f, 0.f, 0.f);
            if (k >= alow[r] && k < Ktot)       // Ktot%4==0 -> vector-exact
                v = *reinterpret_cast<const float4*>(X + abase[r] + k);
            int row = arow + r * 64;
            As[akq + 0][row] = v.x;
            As[akq + 1][row] = v.y;
            As[akq + 2][row] = v.z;
            As[akq + 3][row] = v.w;
        }
        if (bkrow < 16) {
            int k = k0 + bkrow;
            float4 v = make_float4(0.f, 0.f, 0.f, 0.f);
            if (k < Ktot)                       // cols resident (Nw padded)
                v = *reinterpret_cast<const float4*>(Wg + (size_t)k * Nw + bn + bcq);
            *reinterpret_cast<float4*>(&Bs[bkrow][bcq]) = v;
        }
        __syncthreads();

#pragma unroll
        for (int kk = 0; kk < 16; kk++) {
            float4 a0 = *reinterpret_cast<const float4*>(&As[kk][ty * 8]);
            float4 a1 = *reinterpret_cast<const float4*>(&As[kk][ty * 8 + 4]);
            const ull* bp = reinterpret_cast<const ull*>(&Bs[kk][tx * 4]);
            ull b0 = bp[0], b1 = bp[1];
            float av[8] = {a0.x, a0.y, a0.z, a0.w, a1.x, a1.y, a1.z, a1.w};
#pragma unroll
            for (int q = 0; q < 8; q++) {
                ull aa = pack2s(av[q]);
#pragma unroll
                for (int p = 0; p < 2; p++) {
                    ull b  = (p == 0) ? b0 : b1;
                    ull pr = pmul(aa, b);                       // product (rounded)
                    ull s  = acc[q][p];
                    ull t  = padd(s, pr);                       // biased sum
                    ull d  = pfma(s, (ull)NEG1_PK, t);          // d = t - s   (exact)
                    ull e  = pfma(d, (ull)NEG1_PK, pr);         // e = pr - d  (exact)
                    acc[q][p] = t;
                    cmp[q][p] = padd(cmp[q][p], e);
                }
            }
        }
        __syncthreads();
    }

#pragma unroll
    for (int q = 0; q < 8; q++) {
        int m = bm + ty * 8 + q;
#pragma unroll
        for (int p = 0; p < 2; p++) {
            int n = bn + tx * 4 + p * 2;
            float t0, t1, c0, c1;
            unpack2(acc[q][p], t0, t1);
            unpack2(cmp[q][p], c0, c1);
            if (n < N) {
                float v = __fadd_rn(__fsub_rn(t0, CBIAS), c0);
                Y[(size_t)m * N + n] = __fadd_rn(v, bias[n]);
            }
            if (n + 1 < N) {
                float v = __fadd_rn(__fsub_rn(t1, CBIAS), c1);
                Y[(size_t)m * N + n + 1] = __fadd_rn(v, bias[n + 1]);
            }
        }
    }
}

// ---------------------------------------------------------------------------
// LIF scan in fp64 (snntorch Leaky, reset='subtract'). Layout (B,T,C).
// ---------------------------------------------------------------------------
__global__ void lif_kernel(const float* __restrict__ Y, float* __restrict__ S, int C)
{
    int idx = blockIdx.x * blockDim.x + threadIdx.x;
    if (idx >= NB * C) return;
    int b = idx / C;
    int c = idx - b * C;
    const float* y = Y + (size_t)b * NT * C + c;
    float* s = S + (size_t)b * NT * C + c;
    double mem = 0.0;
#pragma unroll
    for (int t = 0; t < NT; t++) {
        double reset = (mem > 1.0) ? 1.0 : 0.0;
        mem = 0.95 * mem + (double)y[t * C] - reset;
        s[t * C] = (mem > 1.0) ? 1.0f : 0.0f;
    }
}

// Final LIF: layer-3 Y has row stride 20 (N=20). Emits spk3 (T,B,20) then mem3.
__global__ void lif_out_kernel(const float* __restrict__ Y, float* __restrict__ out,
                               int out_size)
{
    int idx = blockIdx.x * blockDim.x + threadIdx.x;
    if (idx >= NB * 20) return;
    int b = idx / 20;
    int c = idx - b * 20;
    bool have_mem = (out_size >= 2 * NT * NB * 20);
    double mem = 0.0;
#pragma unroll
    for (int t = 0; t < NT; t++) {
        double reset = (mem > 1.0) ? 1.0 : 0.0;
        mem = 0.95 * mem + (double)Y[((size_t)b * NT + t) * 20 + c] - reset;
        float spk = (mem > 1.0) ? 1.0f : 0.0f;
        out[(size_t)t * NB * 20 + b * 20 + c] = spk;
        if (have_mem)
            out[(size_t)NT * NB * 20 + (size_t)t * NB * 20 + b * 20 + c] = (float)mem;
    }
}

// ---------------------------------------------------------------------------
extern "C" void kernel_launch(void* const* d_in, const int* in_sizes, int n_in,
                              void* d_out, int out_size)
{
    const float* data = (const float*)d_in[0];
    const float* W1   = (const float*)d_in[1];
    const float* b1   = (const float*)d_in[2];
    const float* P1   = (const float*)d_in[3];
    const float* SIG1 = (const float*)d_in[4];
    const float* g1   = (const float*)d_in[5];
    const float* be1  = (const float*)d_in[6];
    const float* mu1  = (const float*)d_in[7];
    const float* va1  = (const float*)d_in[8];
    const float* W2   = (const float*)d_in[9];
    const float* b2   = (const float*)d_in[10];
    const float* P2   = (const float*)d_in[11];
    const float* SIG2 = (const float*)d_in[12];
    const float* g2   = (const float*)d_in[13];
    const float* be2  = (const float*)d_in[14];
    const float* mu2  = (const float*)d_in[15];
    const float* va2  = (const float*)d_in[16];
    const float* W3   = (const float*)d_in[17];
    const float* b3   = (const float*)d_in[18];
    const float* P3   = (const float*)d_in[19];
    const float* SIG3 = (const float*)d_in[20];

    float *Wg1, *Wg2, *Wg3, *bb1, *bb2, *bb3, *Y, *S1, *S2, *Y3;
    cudaGetSymbolAddress((void**)&Wg1, g_Wg1);
    cudaGetSymbolAddress((void**)&Wg2, g_Wg2);
    cudaGetSymbolAddress((void**)&Wg3, g_Wg3);
    cudaGetSymbolAddress((void**)&bb1, g_bb1);
    cudaGetSymbolAddress((void**)&bb2, g_bb2);
    cudaGetSymbolAddress((void**)&bb3, g_bb3);
    cudaGetSymbolAddress((void**)&Y,   g_Y);
    cudaGetSymbolAddress((void**)&S1,  g_S1);
    cudaGetSymbolAddress((void**)&S2,  g_S2);
    cudaGetSymbolAddress((void**)&Y3,  g_Y3);

    // weight/bias prep (tiny). Layer-3 weights padded to 32 cols (zeros).
    zero_buf<<<(K2TOT * 32 + 255) / 256, 256>>>(Wg3, K2TOT * 32);
    prep_weights<<<(256 * 140 + 255) / 256, 256>>>(W1, P1, SIG1, g1, va1, Wg1, 256, 140, 256);
    prep_weights<<<(256 * 256 + 255) / 256, 256>>>(W2, P2, SIG2, g2, va2, Wg2, 256, 256, 256);
    prep_weights<<<(20 * 256 + 255) / 256, 256>>>(W3, P3, SIG3, nullptr, nullptr, Wg3, 20, 256, 32);
    prep_bias<<<1, 256>>>(b1, g1, be1, mu1, va1, bb1, 256);
    prep_bias<<<1, 256>>>(b2, g2, be2, mu2, va2, bb2, 256);
    prep_bias<<<1, 32>>>(b3, nullptr, nullptr, nullptr, nullptr, bb3, 20);

    // layer 1: conv(140->256) + BN folded, then LIF
    conv_gemm_pk<128, 64><<<dim3(200, 4), 256>>>(data, Wg1, bb1, Y, 256, 256, K1TOT, 140);
    lif_kernel<<<(NB * 256 + 255) / 256, 256>>>(Y, S1, 256);

    // layer 2
    conv_gemm_pk<128, 64><<<dim3(200, 4), 256>>>(S1, Wg2, bb2, Y, 256, 256, K2TOT, 256);
    lif_kernel<<<(NB * 256 + 255) / 256, 256>>>(Y, S2, 256);

    // layer 3 (N=20, weight rows padded to 32, no BN)
    conv_gemm_pk<256, 32><<<dim3(100, 1), 256>>>(S2, Wg3, bb3, Y3, 20, 32, K2TOT, 256);
    lif_out_kernel<<<(NB * 20 + 255) / 256, 256>>>(Y3, (float*)d_out, out_size);
}

// round 5
// speedup vs baseline: 2.5446x; 1.2783x over previous
#include <cuda_runtime.h>
#include <cstdint>

// SNN_Delay: 3x (DCLS gaussian 11-tap temporal conv -> [BN] -> LIF scan), forward only.
// Conv = implicit GEMM, biased FastTwoSum compensated accumulation on packed f32x2.
// R5: layers 2/3 (0/1 spike inputs) fuse k-pairs via fma before compensation:
//     6 packed ops / 2 packed terms (vs 5 / 1 term). Layer 1 keeps exact scheme.

typedef unsigned long long ull;

#define NT 25
#define NB 1024
#define MROWS (NB*NT)          // 25600
#define K1TOT (11*140)         // 1540
#define K2TOT (11*256)         // 2816

__device__ float g_Wg1[K1TOT*256];
__device__ float g_Wg2[K2TOT*256];
__device__ float g_Wg3[K2TOT*32];
__device__ float g_bb1[256];
__device__ float g_bb2[256];
__device__ float g_bb3[32];
__device__ float g_Y[MROWS*256];
__device__ float g_S1[MROWS*256];
__device__ float g_S2[MROWS*256];
__device__ float g_Y3[MROWS*20];

// ---------------------------------------------------------------------------
// Weight prep (fp64 internal): dense DCLS kernel, normalized gaussian taps,
// BN scale folded in. Wg layout: [k = j*I + i][o]  (o contiguous, Ostride cols).
// ---------------------------------------------------------------------------
__global__ void prep_weights(const float* __restrict__ W, const float* __restrict__ P,
                             const float* __restrict__ SIG, const float* __restrict__ gamma,
                             const float* __restrict__ var, float* __restrict__ Wg,
                             int O, int I, int Ostride)
{
    int idx = blockIdx.x * blockDim.x + threadIdx.x;
    if (idx >= O * I) return;
    int o = idx / I;
    int i = idx - o * I;
    double pc = (double)P[idx] + 5.0;          // MAXD//2 = 5
    double s  = fabs((double)SIG[idx]) + 0.27;
    double g[11];
    double sum = 0.0;
#pragma unroll
    for (int j = 0; j < 11; j++) {
        double d = ((double)j - pc) / s;
        g[j] = exp(-0.5 * d * d);
        sum += g[j];
    }
    double scale = (double)W[idx] / (sum + 1e-7);
    if (gamma) scale *= (double)gamma[o] / sqrt((double)var[o] + 1e-5);
#pragma unroll
    for (int j = 0; j < 11; j++)
        Wg[(size_t)(j * I + i) * Ostride + o] = (float)(g[j] * scale);
}

__global__ void zero_buf(float* p, int n)
{
    int i = blockIdx.x * blockDim.x + threadIdx.x;
    if (i < n) p[i] = 0.f;
}

__global__ void prep_bias(const float* __restrict__ b, const float* __restrict__ gamma,
                          const float* __restrict__ beta, const float* __restrict__ mean,
                          const float* __restrict__ var, float* __restrict__ out, int O)
{
    int o = blockIdx.x * blockDim.x + threadIdx.x;
    if (o >= O) return;
    double v = (double)b[o];
    if (gamma) {
        double sc = (double)gamma[o] / sqrt((double)var[o] + 1e-5);
        v = (v - (double)mean[o]) * sc + (double)beta[o];
    }
    out[o] = (float)v;
}

// ---------------------------------------------------------------------------
// packed f32x2 helpers
// ---------------------------------------------------------------------------
__device__ __forceinline__ ull pack2s(float a) {
    ull r; asm("mov.b64 %0, {%1,%1};" : "=l"(r) : "f"(a)); return r;
}
__device__ __forceinline__ void unpack2(ull v, float& x, float& y) {
    asm("mov.b64 {%0,%1}, %2;" : "=f"(x), "=f"(y) : "l"(v));
}
__device__ __forceinline__ ull pmul(ull a, ull b) {
    ull r; asm("mul.rn.f32x2 %0, %1, %2;" : "=l"(r) : "l"(a), "l"(b)); return r;
}
__device__ __forceinline__ ull padd(ull a, ull b) {
    ull r; asm("add.rn.f32x2 %0, %1, %2;" : "=l"(r) : "l"(a), "l"(b)); return r;
}
__device__ __forceinline__ ull pfma(ull a, ull b, ull c) {
    ull r; asm("fma.rn.f32x2 %0, %1, %2, %3;" : "=l"(r) : "l"(a), "l"(b), "l"(c)); return r;
}

#define NEG1_PK  0xBF800000BF800000ULL   // (-1.f, -1.f)
#define CBIAS    512.0f
#define CBIAS_PK 0x4400000044000000ULL   // (512.f, 512.f)

// ---------------------------------------------------------------------------
// Implicit-GEMM conv, biased FastTwoSum accumulation, packed f32x2.
// C[m,n] = sum_k U[m,k]*Wg[k,n] + bias[n],
//   U[m,k] = X[(m-10)*I + k] if k >= (10 - m%25)*I else 0.
// Wg rows stride Nw (padded); Y rows stride N.
// PAIR2: fuse 2 consecutive k products with one fma before compensation.
// ---------------------------------------------------------------------------
template<int BM, int BN, bool PAIR2>
__global__ void __launch_bounds__(256)
conv_gemm_pk(const float* __restrict__ X, const float* __restrict__ Wg,
             const float* __restrict__ bias, float* __restrict__ Y,
             int N, int Nw, int Ktot, int I)
{
    static_assert(BM / 64 * 64 == BM, "BM multiple of 64");
    constexpr int APASS = BM / 64;       // row passes for A loads
    constexpr int CG    = BN / 4;        // col groups
    static_assert(256 / CG * 8 == BM, "compute map covers BM");
    __shared__ float As[16][BM + 12];
    __shared__ float Bs[16][BN + 4];

    const int tid = threadIdx.x;
    const int bm = blockIdx.x * BM;
    const int bn = blockIdx.y * BN;

    const int arow = tid >> 2;          // 0..63
    const int akq  = (tid & 3) * 4;     // 0,4,8,12
    long abase[APASS];
    int  alow[APASS];
#pragma unroll
    for (int r = 0; r < APASS; r++) {
        int m = bm + arow + r * 64;
        int t = m % 25;
        abase[r] = (long)(m - 10) * I;
        alow[r]  = (t < 10) ? (10 - t) * I : 0;   // multiple of 4 (I%4==0)
    }
    const int bkrow = tid / CG;
    const int bcq   = (tid % CG) * 4;

    ull acc[8][2], cmp[8][2];
#pragma unroll
    for (int q = 0; q < 8; q++) {
        acc[q][0] = CBIAS_PK; acc[q][1] = CBIAS_PK;
        cmp[q][0] = 0ull;     cmp[q][1] = 0ull;
    }

    const int ty = tid / CG;
    const int tx = tid % CG;

    for (int k0 = 0; k0 < Ktot; k0 += 16) {
#pragma unroll
        for (int r = 0; r < APASS; r++) {
            int k = k0 + akq;
            float4 v = make_float4(0.f, 0.f, 0.f, 0.f);
            if (k >= alow[r] && k < Ktot)
                v = *reinterpret_cast<const float4*>(X + abase[r] + k);
            int row = arow + r * 64;
            As[akq + 0][row] = v.x;
            As[akq + 1][row] = v.y;
            As[akq + 2][row] = v.z;
            As[akq + 3][row] = v.w;
        }
        if (bkrow < 16) {
            int k = k0 + bkrow;
            float4 v = make_float4(0.f, 0.f, 0.f, 0.f);
            if (k < Ktot)
                v = *reinterpret_cast<const float4*>(Wg + (size_t)k * Nw + bn + bcq);
            *reinterpret_cast<float4*>(&Bs[bkrow][bcq]) = v;
        }
        __syncthreads();

        if (PAIR2) {
#pragma unroll
            for (int kk = 0; kk < 16; kk += 2) {
                float4 a00 = *reinterpret_cast<const float4*>(&As[kk][ty * 8]);
                float4 a01 = *reinterpret_cast<const float4*>(&As[kk][ty * 8 + 4]);
                float4 a10 = *reinterpret_cast<const float4*>(&As[kk + 1][ty * 8]);
                float4 a11 = *reinterpret_cast<const float4*>(&As[kk + 1][ty * 8 + 4]);
                const ull* bp0 = reinterpret_cast<const ull*>(&Bs[kk][tx * 4]);
                const ull* bp1 = reinterpret_cast<const ull*>(&Bs[kk + 1][tx * 4]);
                ull b00 = bp0[0], b01 = bp0[1];
                ull b10 = bp1[0], b11 = bp1[1];
                float av0[8] = {a00.x, a00.y, a00.z, a00.w, a01.x, a01.y, a01.z, a01.w};
                float av1[8] = {a10.x, a10.y, a10.z, a10.w, a11.x, a11.y, a11.z, a11.w};
#pragma unroll
                for (int q = 0; q < 8; q++) {
                    ull aa0 = pack2s(av0[q]);
                    ull aa1 = pack2s(av1[q]);
#pragma unroll
                    for (int p = 0; p < 2; p++) {
                        ull bA = (p == 0) ? b00 : b01;
                        ull bB = (p == 0) ? b10 : b11;
                        ull pr = pfma(aa1, bB, pmul(aa0, bA));  // pair product sum
                        ull s  = acc[q][p];
                        ull t  = padd(s, pr);
                        ull d  = pfma(s, (ull)NEG1_PK, t);      // t - s (exact)
                        ull e  = pfma(d, (ull)NEG1_PK, pr);     // pr - d (exact)
                        acc[q][p] = t;
                        cmp[q][p] = padd(cmp[q][p], e);
                    }
                }
            }
        } else {
#pragma unroll
            for (int kk = 0; kk < 16; kk++) {
                float4 a0 = *reinterpret_cast<const float4*>(&As[kk][ty * 8]);
                float4 a1 = *reinterpret_cast<const float4*>(&As[kk][ty * 8 + 4]);
                const ull* bp = reinterpret_cast<const ull*>(&Bs[kk][tx * 4]);
                ull b0 = bp[0], b1 = bp[1];
                float av[8] = {a0.x, a0.y, a0.z, a0.w, a1.x, a1.y, a1.z, a1.w};
#pragma unroll
                for (int q = 0; q < 8; q++) {
                    ull aa = pack2s(av[q]);
#pragma unroll
                    for (int p = 0; p < 2; p++) {
                        ull b  = (p == 0) ? b0 : b1;
                        ull pr = pmul(aa, b);
                        ull s  = acc[q][p];
                        ull t  = padd(s, pr);
                        ull d  = pfma(s, (ull)NEG1_PK, t);
                        ull e  = pfma(d, (ull)NEG1_PK, pr);
                        acc[q][p] = t;
                        cmp[q][p] = padd(cmp[q][p], e);
                    }
                }
            }
        }
        __syncthreads();
    }

#pragma unroll
    for (int q = 0; q < 8; q++) {
        int m = bm + ty * 8 + q;
#pragma unroll
        for (int p = 0; p < 2; p++) {
            int n = bn + tx * 4 + p * 2;
            float t0, t1, c0, c1;
            unpack2(acc[q][p], t0, t1);
            unpack2(cmp[q][p], c0, c1);
            if (n < N) {
                float v = __fadd_rn(__fsub_rn(t0, CBIAS), c0);
                Y[(size_t)m * N + n] = __fadd_rn(v, bias[n]);
            }
            if (n + 1 < N) {
                float v = __fadd_rn(__fsub_rn(t1, CBIAS), c1);
                Y[(size_t)m * N + n + 1] = __fadd_rn(v, bias[n + 1]);
            }
        }
    }
}

// ---------------------------------------------------------------------------
// LIF scan in fp64 (snntorch Leaky, reset='subtract'). Layout (B,T,C).
// ---------------------------------------------------------------------------
__global__ void lif_kernel(const float* __restrict__ Y, float* __restrict__ S, int C)
{
    int idx = blockIdx.x * blockDim.x + threadIdx.x;
    if (idx >= NB * C) return;
    int b = idx / C;
    int c = idx - b * C;
    const float* y = Y + (size_t)b * NT * C + c;
    float* s = S + (size_t)b * NT * C + c;
    double mem = 0.0;
#pragma unroll
    for (int t = 0; t < NT; t++) {
        double reset = (mem > 1.0) ? 1.0 : 0.0;
        mem = 0.95 * mem + (double)y[t * C] - reset;
        s[t * C] = (mem > 1.0) ? 1.0f : 0.0f;
    }
}

// Final LIF: layer-3 Y row stride 20. Emits spk3 (T,B,20) then mem3 (T,B,20).
__global__ void lif_out_kernel(const float* __restrict__ Y, float* __restrict__ out,
                               int out_size)
{
    int idx = blockIdx.x * blockDim.x + threadIdx.x;
    if (idx >= NB * 20) return;
    int b = idx / 20;
    int c = idx - b * 20;
    bool have_mem = (out_size >= 2 * NT * NB * 20);
    double mem = 0.0;
#pragma unroll
    for (int t = 0; t < NT; t++) {
        double reset = (mem > 1.0) ? 1.0 : 0.0;
        mem = 0.95 * mem + (double)Y[((size_t)b * NT + t) * 20 + c] - reset;
        float spk = (mem > 1.0) ? 1.0f : 0.0f;
        out[(size_t)t * NB * 20 + b * 20 + c] = spk;
        if (have_mem)
            out[(size_t)NT * NB * 20 + (size_t)t * NB * 20 + b * 20 + c] = (float)mem;
    }
}

// ---------------------------------------------------------------------------
extern "C" void kernel_launch(void* const* d_in, const int* in_sizes, int n_in,
                              void* d_out, int out_size)
{
    const float* data = (const float*)d_in[0];
    const float* W1   = (const float*)d_in[1];
    const float* b1   = (const float*)d_in[2];
    const float* P1   = (const float*)d_in[3];
    const float* SIG1 = (const float*)d_in[4];
    const float* g1   = (const float*)d_in[5];
    const float* be1  = (const float*)d_in[6];
    const float* mu1  = (const float*)d_in[7];
    const float* va1  = (const float*)d_in[8];
    const float* W2   = (const float*)d_in[9];
    const float* b2   = (const float*)d_in[10];
    const float* P2   = (const float*)d_in[11];
    const float* SIG2 = (const float*)d_in[12];
    const float* g2   = (const float*)d_in[13];
    const float* be2  = (const float*)d_in[14];
    const float* mu2  = (const float*)d_in[15];
    const float* va2  = (const float*)d_in[16];
    const float* W3   = (const float*)d_in[17];
    const float* b3   = (const float*)d_in[18];
    const float* P3   = (const float*)d_in[19];
    const float* SIG3 = (const float*)d_in[20];

    float *Wg1, *Wg2, *Wg3, *bb1, *bb2, *bb3, *Y, *S1, *S2, *Y3;
    cudaGetSymbolAddress((void**)&Wg1, g_Wg1);
    cudaGetSymbolAddress((void**)&Wg2, g_Wg2);
    cudaGetSymbolAddress((void**)&Wg3, g_Wg3);
    cudaGetSymbolAddress((void**)&bb1, g_bb1);
    cudaGetSymbolAddress((void**)&bb2, g_bb2);
    cudaGetSymbolAddress((void**)&bb3, g_bb3);
    cudaGetSymbolAddress((void**)&Y,   g_Y);
    cudaGetSymbolAddress((void**)&S1,  g_S1);
    cudaGetSymbolAddress((void**)&S2,  g_S2);
    cudaGetSymbolAddress((void**)&Y3,  g_Y3);

    // weight/bias prep (tiny). Layer-3 weights padded to 32 cols (zeros).
    zero_buf<<<(K2TOT * 32 + 255) / 256, 256>>>(Wg3, K2TOT * 32);
    prep_weights<<<(256 * 140 + 255) / 256, 256>>>(W1, P1, SIG1, g1, va1, Wg1, 256, 140, 256);
    prep_weights<<<(256 * 256 + 255) / 256, 256>>>(W2, P2, SIG2, g2, va2, Wg2, 256, 256, 256);
    prep_weights<<<(20 * 256 + 255) / 256, 256>>>(W3, P3, SIG3, nullptr, nullptr, Wg3, 20, 256, 32);
    prep_bias<<<1, 256>>>(b1, g1, be1, mu1, va1, bb1, 256);
    prep_bias<<<1, 256>>>(b2, g2, be2, mu2, va2, bb2, 256);
    prep_bias<<<1, 32>>>(b3, nullptr, nullptr, nullptr, nullptr, bb3, 20);

    // layer 1: dense gaussian inputs -> exact per-term compensation
    conv_gemm_pk<128, 64, false><<<dim3(200, 4), 256>>>(data, Wg1, bb1, Y, 256, 256, K1TOT, 140);
    lif_kernel<<<(NB * 256 + 255) / 256, 256>>>(Y, S1, 256);

    // layer 2: spike inputs -> pair-fused compensation
    conv_gemm_pk<128, 64, true><<<dim3(200, 4), 256>>>(S1, Wg2, bb2, Y, 256, 256, K2TOT, 256);
    lif_kernel<<<(NB * 256 + 255) / 256, 256>>>(Y, S2, 256);

    // layer 3: spike inputs, N=20 (weight rows padded to 32), no BN
    conv_gemm_pk<256, 32, true><<<dim3(100, 1), 256>>>(S2, Wg3, bb3, Y3, 20, 32, K2TOT, 256);
    lif_out_kernel<<<(NB * 20 + 255) / 256, 256>>>(Y3, (float*)d_out, out_size);
}